// round 17
// baseline (speedup 1.0000x reference)
#include <cuda_runtime.h>
#include <cstdint>
#include <math.h>

#define GO_TAG 1
#define NEGV   -10000.0f
#define K_     64
#define MAXELEMS_ (1024u * 512u * 64u)
#define ORDER_MAX 65536
#define NWORK_BLOCKS 444   // 3 per SM on 148-SM GB300 (measured optimum)

// Scratch: alpha history, trans tables, scheduler, backward work queue.
__device__ float g_trans[K_ * K_];    // trans[i][j] = score(i -> j)
__device__ float g_transT[K_ * K_];   // transT[j][i] = trans[i][j]
__device__ float g_alpha[MAXELEMS_];
__device__ int   g_ctr;               // forward claim counter
__device__ int   g_order[ORDER_MAX];  // LPT order
__device__ int   g_bw;                // backward queue write counter
__device__ int   g_br;                // backward queue read counter
__device__ int   g_bq_b[ORDER_MAX];   // payload: sequence index b
__device__ int   g_bq_flag[ORDER_MAX];// 0 = empty, else last+1

__device__ __forceinline__ void cp_async16(uint32_t saddr, const void* gptr) {
    asm volatile("cp.async.ca.shared.global [%0], [%1], 16;"
                 :: "r"(saddr), "l"(gptr));
}
__device__ __forceinline__ void cp_commit() {
    asm volatile("cp.async.commit_group;");
}
template <int N>
__device__ __forceinline__ void cp_wait() {
    asm volatile("cp.async.wait_group %0;" :: "n"(N));
}

// ---------------------------------------------------------------------------
// Fused prelude: blocks 0..63 -> log_softmax row; block 64 -> LPT counting
// sort + reset counters + zero backward-queue flags.
// ---------------------------------------------------------------------------
__global__ void __launch_bounds__(1024)
prelude_kernel(const float* __restrict__ c0, const float* __restrict__ c1,
               const int* __restrict__ lengths, int T, int B) {
    const int tid = threadIdx.x;

    if (blockIdx.x < 64) {
        __shared__ float  s_m[2];
        __shared__ double s_s[2];
        const int r = blockIdx.x;
        const int c = tid;
        const bool active = (c < K_);
        const int w = c >> 5;
        const int lane = c & 31;

        unsigned u0 = active ? ((const unsigned*)c0)[r * K_ + c] : 0u;
        const bool c0_is_mask = __syncthreads_and(u0 <= 1u);
        const int*   mask = (const int*)(c0_is_mask ? c0 : c1);
        const float* A    = c0_is_mask ? c1 : c0;

        if (active) {
            float x = A[r * K_ + c] + (mask[r * K_ + c] ? NEGV : 0.0f);
            float m = x;
            #pragma unroll
            for (int d = 16; d > 0; d >>= 1)
                m = fmaxf(m, __shfl_xor_sync(~0u, m, d));
            if (lane == 0) s_m[w] = m;
        }
        __syncthreads();
        if (active) {
            float x = A[r * K_ + c] + (mask[r * K_ + c] ? NEGV : 0.0f);
            float m = fmaxf(s_m[0], s_m[1]);
            double e = exp((double)(x - m));
            #pragma unroll
            for (int d = 16; d > 0; d >>= 1) e += __shfl_xor_sync(~0u, e, d);
            if (lane == 0) s_s[w] = e;
        }
        __syncthreads();
        if (active) {
            float x = A[r * K_ + c] + (mask[r * K_ + c] ? NEGV : 0.0f);
            float m = fmaxf(s_m[0], s_m[1]);
            const float l = (float)log(s_s[0] + s_s[1]);
            const float v = (x - m) - l;
            g_trans[r * K_ + c]  = v;
            g_transT[c * K_ + r] = v;
        }
    } else {
        __shared__ int h[1024];
        __shared__ int h2[1024];
        __shared__ int cur[1024];
        if (tid == 0) { g_ctr = 0; g_bw = 0; g_br = 0; }
        h[tid] = 0;
        // zero backward-queue flags for this launch (graph-replayed)
        int bmax = B < ORDER_MAX ? B : ORDER_MAX;
        for (int i = tid; i < bmax; i += 1024) g_bq_flag[i] = 0;
        __syncthreads();

        for (int i = tid; i < B; i += 1024) {
            int len = lengths[i]; len = len < 1 ? 1 : (len > T ? T : len);
            int key = T - len; key = key < 0 ? 0 : (key > 1023 ? 1023 : key);
            atomicAdd(&h[key], 1);
        }
        __syncthreads();

        const int cnt = h[tid];
        int* src = h;
        int* dst = h2;
        for (int d = 1; d < 1024; d <<= 1) {
            int v = src[tid];
            if (tid >= d) v += src[tid - d];
            dst[tid] = v;
            __syncthreads();
            int* tmp = src; src = dst; dst = tmp;
        }
        cur[tid] = src[tid] - cnt;
        __syncthreads();

        for (int i = tid; i < B; i += 1024) {
            int len = lengths[i]; len = len < 1 ? 1 : (len > T ? T : len);
            int key = T - len; key = key < 0 ? 0 : (key > 1023 ? 1023 : key);
            int pos = atomicAdd(&cur[key], 1);
            if (pos < ORDER_MAX) g_order[pos] = i;
        }
    }
}

// ---------------------------------------------------------------------------
// Backward task (one warp): tail fill + path-recompute decode.
// sbg: warp-private smem stage [2][4][K_] floats (generic pointer).
// ---------------------------------------------------------------------------
__device__ void backward_task(int lane, int T, int len, int last,
                              float* __restrict__ ob,
                              const float* __restrict__ arow,
                              float* sbg, const float* __restrict__ s_transT) {
    const float lastf = (float)last;
    for (int tau = (len - 1) + lane; tau < T; tau += 32) ob[tau] = lastf;
    if (len < 2) return;

    const uint32_t sb = (uint32_t)__cvta_generic_to_shared(sbg);
    int tag = last;

    // prefetch rows len-1-s, s=0..3 (4 rows x 256B = 2 cp.async per lane)
    #pragma unroll
    for (int rr = 0; rr < 2; rr++) {
        int l = lane + rr * 32;
        int s = l >> 4;
        int c = (l & 15) * 4;
        int row = len - 1 - s; if (row < 0) row = 0;
        cp_async16(sb + (uint32_t)(s * K_ + c) * 4,
                   arow + (size_t)row * K_ + c);
    }
    cp_commit();

    int bbuf = 0;
    for (int tb = len; tb >= 2; tb -= 4) {
        if (tb - 4 >= 2) {
            #pragma unroll
            for (int rr = 0; rr < 2; rr++) {
                int l = lane + rr * 32;
                int s = l >> 4;
                int c = (l & 15) * 4;
                int row = tb - 5 - s; if (row < 0) row = 0;
                cp_async16(sb + (uint32_t)(((bbuf ^ 1) * 4 + s) * K_ + c) * 4,
                           arow + (size_t)row * K_ + c);
            }
        }
        cp_commit();
        cp_wait<1>();
        __syncwarp();

        const int tlo = (tb - 3 > 2) ? tb - 3 : 2;
        #pragma unroll
        for (int s = 0; s < 4; s++) {
            const int t = tb - s;
            if (t >= tlo) {
                float2 a = ((const float2*)(sbg + (bbuf * 4 + s) * K_))[lane];
                float2 tt = ((const float2*)(s_transT + tag * K_))[lane];
                float c0 = a.x + tt.x;
                float c1 = a.y + tt.y;
                float v; int li;
                if (c0 >= c1) { v = c0; li = 2 * lane; }
                else          { v = c1; li = 2 * lane + 1; }
                unsigned bits = __float_as_uint(v);
                unsigned key = ((int)bits < 0) ? ~bits : (bits | 0x80000000u);
                unsigned mx = __reduce_max_sync(0xffffffffu, key);
                unsigned sel = (key == mx) ? (unsigned)(K_ - 1 - li) : 0u;
                unsigned w = __reduce_max_sync(0xffffffffu, sel);
                tag = (K_ - 1) - (int)w;
                if (lane == 0) ob[t - 2] = (float)tag;
            }
        }
        bbuf ^= 1;
    }
}

// ---------------------------------------------------------------------------
// Kernel 2: PERSISTENT Viterbi, forward/backward decoupled via work queue.
// 128-thread block = 2 forward groups of 64. Groups do forwards only and
// publish (b, last) to the backward queue; when the forward queue drains,
// each warp independently pulls backward tasks and decodes them in parallel.
// ---------------------------------------------------------------------------
__global__ void __launch_bounds__(128)
viterbi_kernel(const float* __restrict__ unary,
               const int* __restrict__ lengths,
               float* __restrict__ out,
               int T, int B) {
    __shared__ __align__(16) float s_transT[K_ * K_];
    __shared__ __align__(16) float s_alpha[2][2][K_];    // [g][buf][j]
    __shared__ __align__(16) float s_u[2][2][8][K_];     // [g][buf][s][j]
    __shared__ __align__(16) float s_bw[4][2 * 4 * K_];  // per-warp bwd stage
    __shared__ int s_idx[2];

    const int tid = threadIdx.x;
    const int g = tid >> 6;
    const int j = tid & 63;
    const int wb = tid >> 5;        // block warp id 0..3
    const int lane = tid & 31;
    const int nbar = 1 + g;

    #define GBAR() asm volatile("bar.sync %0, 64;" :: "r"(nbar) : "memory")

    const uint32_t su_base =
        (uint32_t)__cvta_generic_to_shared(&s_u[g][0][0][0]);
    const size_t bstride = (size_t)T * K_;

    // One-time: shared transposed table + register transition column.
    {
        const float4* src = (const float4*)g_transT;
        float4* dst = (float4*)s_transT;
        #pragma unroll
        for (int q = 0; q < 8; q++) dst[tid + q * 128] = src[tid + q * 128];
    }
    float tr[K_];
    #pragma unroll
    for (int i = 0; i < K_; i++) tr[i] = g_trans[i * K_ + j];
    __syncthreads();

    // -------------------- forward-producer loop --------------------
    for (;;) {
        if (j == 0) s_idx[g] = atomicAdd(&g_ctr, 1);
        GBAR();
        const int idx = s_idx[g];
        if (idx >= B) break;                 // uniform per group
        const int b = g_order[idx];

        int len = lengths[b];
        len = len < 1 ? 1 : (len > T ? T : len);
        const float* ub = unary + (size_t)b * bstride;
        float* arow = g_alpha + (size_t)b * bstride;

        // Prefetch first unary chunk (steps 1..8 -> rows 0..7, clamped).
        {
            #pragma unroll
            for (int rr = 0; rr < 2; rr++) {
                int l = j + rr * 64;
                int s = l >> 4;
                int c = (l & 15) * 4;
                int row = s; if (row > T - 1) row = T - 1;
                cp_async16(su_base + (uint32_t)(s * K_ + c) * 4,
                           ub + (size_t)row * K_ + c);
            }
            cp_commit();
        }

        s_alpha[g][0][j] = (j == GO_TAG) ? 0.0f : NEGV;
        GBAR();

        int cbuf = 0;
        for (int t0 = 1; t0 <= len; t0 += 8) {
            if (t0 + 8 <= len) {
                #pragma unroll
                for (int rr = 0; rr < 2; rr++) {
                    int l = j + rr * 64;
                    int s = l >> 4;
                    int c = (l & 15) * 4;
                    int row = t0 + 7 + s;
                    if (row > T - 1) row = T - 1;
                    cp_async16(su_base + (uint32_t)(((cbuf ^ 1) * 8 + s) * K_ + c) * 4,
                               ub + (size_t)row * K_ + c);
                }
            }
            cp_commit();      // always commit (possibly empty)
            cp_wait<1>();     // current chunk complete
            GBAR();

            const int tend = (t0 + 7 < len) ? t0 + 7 : len;
            #pragma unroll
            for (int s = 0; s < 8; s++) {
                const int t = t0 + s;
                if (t <= tend) {             // uniform per group
                    const float u = s_u[g][cbuf][s][j];
                    const float4* av = (const float4*)s_alpha[g][(t - 1) & 1];
                    float4 v = av[0];
                    float m0 = v.x + tr[0];
                    float m1 = v.y + tr[1];
                    float m2 = v.z + tr[2];
                    float m3 = v.w + tr[3];
                    #pragma unroll
                    for (int q = 1; q < 16; q++) {
                        v = av[q];
                        m0 = fmaxf(m0, v.x + tr[4 * q + 0]);
                        m1 = fmaxf(m1, v.y + tr[4 * q + 1]);
                        m2 = fmaxf(m2, v.z + tr[4 * q + 2]);
                        m3 = fmaxf(m3, v.w + tr[4 * q + 3]);
                    }
                    float a = fmaxf(fmaxf(m0, m1), fmaxf(m2, m3)) + u;
                    s_alpha[g][t & 1][j] = a;
                    if (t < len) arow[(size_t)t * K_ + j] = a;  // rows 1..len-1
                    GBAR();
                }
            }
            cbuf ^= 1;
        }

        // argmax (j==0) + publish to backward queue.
        int bi = 0;
        if (j == 0) {
            const float* af = s_alpha[g][len & 1];
            float bv = af[0];
            #pragma unroll
            for (int i = 1; i < K_; i++) {
                if (af[i] > bv) { bv = af[i]; bi = i; }
            }
        }
        __threadfence();   // make this group's g_alpha rows globally visible
        GBAR();            // all fences done; s_alpha free for next claim
        if (j == 0) {
            int wslot = atomicAdd(&g_bw, 1);
            if (wslot < ORDER_MAX) {
                g_bq_b[wslot] = b;
                __threadfence();
                ((volatile int*)g_bq_flag)[wslot] = bi + 1;
            }
        }
    }

    // -------------------- backward-consumer loop (per warp) ----------------
    float* sbg = &s_bw[wb][0];
    for (;;) {
        int r = 0;
        if (lane == 0) r = atomicAdd(&g_br, 1);
        r = __shfl_sync(0xffffffffu, r, 0);
        if (r >= B || r >= ORDER_MAX) break;

        int v = 0;
        int b = 0;
        if (lane == 0) {
            while ((v = ((volatile int*)g_bq_flag)[r]) == 0) __nanosleep(64);
            __threadfence();
            b = ((volatile int*)g_bq_b)[r];
        }
        v = __shfl_sync(0xffffffffu, v, 0);
        b = __shfl_sync(0xffffffffu, b, 0);
        __threadfence();   // acquire before reading g_alpha rows

        const int last = v - 1;
        int len = lengths[b];
        len = len < 1 ? 1 : (len > T ? T : len);

        backward_task(lane, T, len, last,
                      out + (size_t)b * T,
                      g_alpha + (size_t)b * bstride,
                      sbg, s_transT);
    }
    #undef GBAR
}

extern "C" void kernel_launch(void* const* d_in, const int* in_sizes, int n_in,
                              void* d_out, int out_size) {
    // ----- identify inputs by SIZE, not position -----
    int iu = 0;
    for (int i = 1; i < n_in; i++)
        if (in_sizes[i] > in_sizes[iu]) iu = i;

    int pair[2] = {-1, -1};
    int ilen = -1;
    for (int i = 0; i < n_in; i++) {
        if (i == iu) continue;
        for (int k = 0; k < n_in; k++) {
            if (k == i || k == iu) continue;
            if (in_sizes[k] == in_sizes[i]) { pair[0] = i < k ? i : k; pair[1] = i < k ? k : i; }
        }
    }
    for (int i = 0; i < n_in; i++)
        if (i != iu && i != pair[0] && i != pair[1]) ilen = i;
    if (ilen < 0) { iu = 0; ilen = 1; pair[0] = 2; pair[1] = 3; }

    const float* unary   = (const float*)d_in[iu];
    const int*   lengths = (const int*)d_in[ilen];
    const float* c0      = (const float*)d_in[pair[0]];
    const float* c1      = (const float*)d_in[pair[1]];
    float* out = (float*)d_out;

    const int B = in_sizes[ilen];
    const int T = (int)((long long)in_sizes[iu] / ((long long)B * K_));

    prelude_kernel<<<65, 1024>>>(c0, c1, lengths, T, B);
    viterbi_kernel<<<NWORK_BLOCKS, 128>>>(unary, lengths, out, T, B);
}